// round 7
// baseline (speedup 1.0000x reference)
#include <cuda_runtime.h>
#include <cstdint>

// NeRF volume renderer.
//   sigma (R,192,1) f32, color (R,192,3) f32, t (R,192,1) f32
//   -> out: [rgb (R*3) | depth (R)] f32.
//
// color identified host-side by element count (3x). sigma vs t disambiguated
// on-device (t is sorted nondecreasing and >= 2; N(0,1) sigma is not).
//
// Block = 8 rays. Stage all three arrays block-contiguously into smem with
// float4 loads (perfect coalescing, 1 wavefront per LDG.128), then run the
// R6-validated warp-per-ray compositing from smem:
//   per-lane sequential "over" on 6 contiguous samples, exclusive
//   multiplicative warp scan of segment transmittance, warp sum.

#define N_SAMPLES 192
#define SPL 6                 // samples per lane (32*6 = 192)
#define RPB 8                 // rays per block
#define THREADS 256
#define FULL 0xffffffffu

__device__ int g_t_is_a;      // 1 if pa is t, else 0

__global__ void detect_kernel(const float* __restrict__ a)
{
    const int lane = threadIdx.x;
    int is_t = 1;
    for (int i = lane; i < N_SAMPLES - 1; i += 32)
        if (a[i] > a[i + 1]) is_t = 0;
    if (a[0] < 1.5f) is_t = 0;          // t in [2,6]
    unsigned m = __ballot_sync(FULL, is_t);
    if (lane == 0) g_t_is_a = (m == FULL) ? 1 : 0;
}

__global__ __launch_bounds__(THREADS) void render_kernel(
    const float* __restrict__ pa,      // sigma or t
    const float* __restrict__ pb,      // the other one
    const float* __restrict__ color,
    float* __restrict__ out,
    int n_rays)
{
    // Linear smem layout, identity staging (no index math on the copy path).
    __shared__ float sh_sig[RPB * N_SAMPLES];        // [8][192]
    __shared__ float sh_t  [RPB * N_SAMPLES];        // [8][192]
    __shared__ float sh_col[RPB * N_SAMPLES * 3];    // [8][576]

    const int flag = g_t_is_a;
    const float* __restrict__ sigma = flag ? pb : pa;
    const float* __restrict__ t     = flag ? pa : pb;

    const int tid  = threadIdx.x;
    const int w    = tid >> 5;          // warp = local ray
    const int lane = tid & 31;
    const int ray_base = blockIdx.x * RPB;

    // ---- Stage: fully coalesced float4 copies of the block's contiguous regions
    if (ray_base + RPB <= n_rays) {
        const float4* gs = (const float4*)(sigma + (size_t)ray_base * N_SAMPLES);
        const float4* gt = (const float4*)(t     + (size_t)ray_base * N_SAMPLES);
        const float4* gc = (const float4*)(color + (size_t)ray_base * N_SAMPLES * 3);
#pragma unroll
        for (int v = tid; v < RPB * N_SAMPLES / 4; v += THREADS) {       // 384
            ((float4*)sh_sig)[v] = gs[v];
            ((float4*)sh_t  )[v] = gt[v];
        }
#pragma unroll
        for (int v = tid; v < RPB * N_SAMPLES * 3 / 4; v += THREADS)     // 1152
            ((float4*)sh_col)[v] = gc[v];
    } else {
        // guarded scalar tail path (rare / typically unused)
        for (int i = tid; i < RPB * N_SAMPLES; i += THREADS) {
            int ray = ray_base + i / N_SAMPLES;
            float vs = 0.0f, vt = 0.0f;
            if (ray < n_rays) {
                vs = sigma[(size_t)ray_base * N_SAMPLES + i];
                vt = t    [(size_t)ray_base * N_SAMPLES + i];
            }
            sh_sig[i] = vs; sh_t[i] = vt;
        }
        for (int i = tid; i < RPB * N_SAMPLES * 3; i += THREADS) {
            int ray = ray_base + i / (N_SAMPLES * 3);
            sh_col[i] = (ray < n_rays)
                ? color[(size_t)ray_base * N_SAMPLES * 3 + i] : 0.0f;
        }
    }
    __syncthreads();

    const int my_ray = ray_base + w;
    if (my_ray >= n_rays) return;

    const float* __restrict__ ss = sh_sig + w * N_SAMPLES + lane * SPL;
    const float* __restrict__ st = sh_t   + w * N_SAMPLES + lane * SPL;
    const float* __restrict__ sc = sh_col + w * (N_SAMPLES * 3) + lane * (SPL * 3);

    float sv[SPL], tv[SPL + 1], cv[SPL * 3];
#pragma unroll
    for (int j = 0; j < SPL; j++) { sv[j] = ss[j]; tv[j] = st[j]; }
    tv[SPL] = (lane < 31) ? st[SPL] : 0.0f;
#pragma unroll
    for (int j = 0; j < SPL * 3; j++) cv[j] = sc[j];

    // ---- Local sequential compositing (R6-validated math)
    float Tl = 1.0f;
    float r = 0.0f, g = 0.0f, b = 0.0f, d = 0.0f;
#pragma unroll
    for (int j = 0; j < SPL; j++) {
        float sg = fmaxf(sv[j], 0.0f);
        float delta = (lane == 31 && j == SPL - 1) ? 1e10f : (tv[j + 1] - tv[j]);
        float om = __expf(-sg * delta);        // = 1 - alpha
        float wgt = Tl * (1.0f - om);
        r = fmaf(wgt, cv[j * 3 + 0], r);
        g = fmaf(wgt, cv[j * 3 + 1], g);
        b = fmaf(wgt, cv[j * 3 + 2], b);
        d = fmaf(wgt, tv[j], d);
        Tl *= om;
    }

    // ---- Exclusive prefix product of Tl across lanes
    float e = __shfl_up_sync(FULL, Tl, 1);
    if (lane == 0) e = 1.0f;
#pragma unroll
    for (int off = 1; off < 32; off <<= 1) {
        float y = __shfl_up_sync(FULL, e, off);
        if (lane >= off) e *= y;
    }

    r *= e; g *= e; b *= e; d *= e;
#pragma unroll
    for (int off = 16; off > 0; off >>= 1) {
        r += __shfl_down_sync(FULL, r, off);
        g += __shfl_down_sync(FULL, g, off);
        b += __shfl_down_sync(FULL, b, off);
        d += __shfl_down_sync(FULL, d, off);
    }

    if (lane == 0) {
        out[(size_t)my_ray * 3 + 0] = r;
        out[(size_t)my_ray * 3 + 1] = g;
        out[(size_t)my_ray * 3 + 2] = b;
        out[(size_t)n_rays * 3 + my_ray] = d;
    }
}

extern "C" void kernel_launch(void* const* d_in, const int* in_sizes, int n_in,
                              void* d_out, int out_size)
{
    // color = largest input; the other two are sigma/t (disambiguated on device).
    int color_idx = 0;
    for (int i = 1; i < 3; i++)
        if (in_sizes[i] > in_sizes[color_idx]) color_idx = i;

    int a_idx = -1, b_idx = -1;
    for (int i = 0; i < 3; i++) {
        if (i == color_idx) continue;
        if (a_idx < 0) a_idx = i; else b_idx = i;
    }

    const float* pa    = (const float*)d_in[a_idx];
    const float* pb    = (const float*)d_in[b_idx];
    const float* color = (const float*)d_in[color_idx];
    float* out = (float*)d_out;

    int n_rays = in_sizes[a_idx] / N_SAMPLES;

    detect_kernel<<<1, 32>>>(pa);

    int blocks = (n_rays + RPB - 1) / RPB;
    render_kernel<<<blocks, THREADS>>>(pa, pb, color, out, n_rays);
}

// round 8
// speedup vs baseline: 1.2730x; 1.2730x over previous
#include <cuda_runtime.h>
#include <cstdint>

// NeRF volume renderer.
//   sigma (R,192,1) f32, color (R,192,3) f32, t (R,192,1) f32
//   -> out: [rgb (R*3) | depth (R)] f32.
//
// color identified host-side by element count (3x). sigma vs t disambiguated
// inline (t is sorted nondecreasing and >= 2; N(0,1) sigma is not) via 8
// warp-uniform probe loads — no separate detection kernel.
//
// WARP-PER-RAY (R6-validated): 6 contiguous samples per lane, sequential
// reference math per lane, exclusive multiplicative warp scan of segment
// transmittance, warp sum. __launch_bounds__(256,4) gives ptxas ~64 regs so
// all 15 per-thread loads stay concurrently in flight (MLP ~15).

#define N_SAMPLES 192
#define SPL 6               // samples per lane (32*6 = 192)
#define FULL 0xffffffffu

__global__ __launch_bounds__(256, 4) void render_kernel(
    const float* __restrict__ pa,      // sigma or t
    const float* __restrict__ pb,      // the other one
    const float* __restrict__ color,
    float* __restrict__ out,
    int n_rays)
{
    const int warp_id = (blockIdx.x * blockDim.x + threadIdx.x) >> 5;  // = ray
    const int lane = threadIdx.x & 31;
    if (warp_id >= n_rays) return;

    // ---- Inline sigma/t disambiguation: pa is t iff pa[0..7] monotone
    // nondecreasing and pa[0] >= 1.5. Uniform addresses -> broadcast loads.
    bool is_t = (pa[0] >= 1.5f);
#pragma unroll
    for (int i = 0; i < 7; i++) is_t = is_t && (pa[i] <= pa[i + 1]);

    const float* __restrict__ sigma = is_t ? pb : pa;
    const float* __restrict__ t     = is_t ? pa : pb;

    const size_t ray = (size_t)warp_id;
    const float* __restrict__ sp = sigma + ray * N_SAMPLES + lane * SPL;
    const float* __restrict__ tp = t     + ray * N_SAMPLES + lane * SPL;
    const float* __restrict__ cp = color + ray * (N_SAMPLES * 3) + lane * (SPL * 3);

    // ---- Issue all loads up front (float2; 24*lane / 72*lane byte offsets are 8B-aligned)
    float sv[SPL], tv[SPL + 1], cv[SPL * 3];
#pragma unroll
    for (int j = 0; j < SPL; j += 2) {
        float2 v = *(const float2*)(sp + j);
        sv[j] = v.x; sv[j + 1] = v.y;
        float2 u = *(const float2*)(tp + j);
        tv[j] = u.x; tv[j + 1] = u.y;
    }
#pragma unroll
    for (int j = 0; j < SPL * 3; j += 2) {
        float2 v = *(const float2*)(cp + j);
        cv[j] = v.x; cv[j + 1] = v.y;
    }
    // boundary t: first sample of the next lane's segment (never needed by lane 31;
    // guarded to avoid OOB on the last ray)
    tv[SPL] = (lane < 31) ? tp[SPL] : 0.0f;

    // ---- Local sequential compositing over this lane's 6 samples
    float Tl = 1.0f;
    float r = 0.0f, g = 0.0f, b = 0.0f, d = 0.0f;
#pragma unroll
    for (int j = 0; j < SPL; j++) {
        float sg = fmaxf(sv[j], 0.0f);
        float delta = (lane == 31 && j == SPL - 1) ? 1e10f : (tv[j + 1] - tv[j]);
        float om = __expf(-sg * delta);        // = 1 - alpha
        float w  = Tl * (1.0f - om);
        r = fmaf(w, cv[j * 3 + 0], r);
        g = fmaf(w, cv[j * 3 + 1], g);
        b = fmaf(w, cv[j * 3 + 2], b);
        d = fmaf(w, tv[j], d);
        Tl *= om;                              // segment transmittance product
    }

    // ---- Exclusive prefix product of Tl across lanes
    float e = __shfl_up_sync(FULL, Tl, 1);
    if (lane == 0) e = 1.0f;
#pragma unroll
    for (int off = 1; off < 32; off <<= 1) {
        float y = __shfl_up_sync(FULL, e, off);
        if (lane >= off) e *= y;
    }

    // Scale per-segment accumulators by entering transmittance, then warp sum.
    r *= e; g *= e; b *= e; d *= e;
#pragma unroll
    for (int off = 16; off > 0; off >>= 1) {
        r += __shfl_down_sync(FULL, r, off);
        g += __shfl_down_sync(FULL, g, off);
        b += __shfl_down_sync(FULL, b, off);
        d += __shfl_down_sync(FULL, d, off);
    }

    if (lane == 0) {
        out[ray * 3 + 0] = r;
        out[ray * 3 + 1] = g;
        out[ray * 3 + 2] = b;
        out[(size_t)n_rays * 3 + ray] = d;
    }
}

extern "C" void kernel_launch(void* const* d_in, const int* in_sizes, int n_in,
                              void* d_out, int out_size)
{
    // color = largest input; the other two are sigma/t (disambiguated on device).
    int color_idx = 0;
    for (int i = 1; i < 3; i++)
        if (in_sizes[i] > in_sizes[color_idx]) color_idx = i;

    int a_idx = -1, b_idx = -1;
    for (int i = 0; i < 3; i++) {
        if (i == color_idx) continue;
        if (a_idx < 0) a_idx = i; else b_idx = i;
    }

    const float* pa    = (const float*)d_in[a_idx];
    const float* pb    = (const float*)d_in[b_idx];
    const float* color = (const float*)d_in[color_idx];
    float* out = (float*)d_out;

    int n_rays = in_sizes[a_idx] / N_SAMPLES;

    const int threads = 256;                      // 8 warps = 8 rays per block
    long long total_threads = (long long)n_rays * 32;
    int blocks = (int)((total_threads + threads - 1) / threads);
    render_kernel<<<blocks, threads>>>(pa, pb, color, out, n_rays);
}

// round 9
// speedup vs baseline: 1.2819x; 1.0069x over previous
#include <cuda_runtime.h>
#include <cstdint>

// NeRF volume renderer.
//   sigma (R,192,1) f32, color (R,192,3) f32, t (R,192,1) f32
//   -> out: [rgb (R*3) | depth (R)] f32.
//
// color identified host-side by element count (3x). sigma vs t disambiguated
// inline (t is sorted nondecreasing and >= 2; N(0,1) sigma is not) via 8
// warp-uniform probe loads.
//
// WARP-PER-RAY: 6 contiguous samples per lane, sequential reference math per
// lane, exclusive multiplicative warp scan of segment transmittance, warp sum.
// __launch_bounds__(256,3) -> up to 84 regs/thread so ALL 15 per-thread float2
// loads are concurrently in flight (MLP ~15); latency-hiding via MLP, not occ.

#define N_SAMPLES 192
#define SPL 6               // samples per lane (32*6 = 192)
#define FULL 0xffffffffu

__global__ __launch_bounds__(256, 3) void render_kernel(
    const float* __restrict__ pa,      // sigma or t
    const float* __restrict__ pb,      // the other one
    const float* __restrict__ color,
    float* __restrict__ out,
    int n_rays)
{
    const int warp_id = (blockIdx.x * blockDim.x + threadIdx.x) >> 5;  // = ray
    const int lane = threadIdx.x & 31;
    if (warp_id >= n_rays) return;

    // ---- Inline sigma/t disambiguation: pa is t iff pa[0..7] monotone
    // nondecreasing and pa[0] >= 1.5. Uniform addresses -> broadcast loads (L2-hot).
    bool is_t = (pa[0] >= 1.5f);
#pragma unroll
    for (int i = 0; i < 7; i++) is_t = is_t && (pa[i] <= pa[i + 1]);

    const float* __restrict__ sigma = is_t ? pb : pa;
    const float* __restrict__ t     = is_t ? pa : pb;

    const size_t ray = (size_t)warp_id;
    const float* __restrict__ sp = sigma + ray * N_SAMPLES + lane * SPL;
    const float* __restrict__ tp = t     + ray * N_SAMPLES + lane * SPL;
    const float* __restrict__ cp = color + ray * (N_SAMPLES * 3) + lane * (SPL * 3);

    // ---- Issue all loads up front (float2; 24*lane / 72*lane byte offsets are 8B-aligned)
    float sv[SPL], tv[SPL + 1], cv[SPL * 3];
#pragma unroll
    for (int j = 0; j < SPL; j += 2) {
        float2 v = *(const float2*)(sp + j);
        sv[j] = v.x; sv[j + 1] = v.y;
        float2 u = *(const float2*)(tp + j);
        tv[j] = u.x; tv[j + 1] = u.y;
    }
#pragma unroll
    for (int j = 0; j < SPL * 3; j += 2) {
        float2 v = *(const float2*)(cp + j);
        cv[j] = v.x; cv[j + 1] = v.y;
    }
    // boundary t: first sample of the next lane's segment (never needed by lane 31;
    // guarded to avoid OOB on the last ray)
    tv[SPL] = (lane < 31) ? tp[SPL] : 0.0f;

    // ---- Local sequential compositing over this lane's 6 samples
    float Tl = 1.0f;
    float r = 0.0f, g = 0.0f, b = 0.0f, d = 0.0f;
#pragma unroll
    for (int j = 0; j < SPL; j++) {
        float sg = fmaxf(sv[j], 0.0f);
        float delta = (lane == 31 && j == SPL - 1) ? 1e10f : (tv[j + 1] - tv[j]);
        float om = __expf(-sg * delta);        // = 1 - alpha
        float w  = Tl * (1.0f - om);
        r = fmaf(w, cv[j * 3 + 0], r);
        g = fmaf(w, cv[j * 3 + 1], g);
        b = fmaf(w, cv[j * 3 + 2], b);
        d = fmaf(w, tv[j], d);
        Tl *= om;                              // segment transmittance product
    }

    // ---- Exclusive prefix product of Tl across lanes
    float e = __shfl_up_sync(FULL, Tl, 1);
    if (lane == 0) e = 1.0f;
#pragma unroll
    for (int off = 1; off < 32; off <<= 1) {
        float y = __shfl_up_sync(FULL, e, off);
        if (lane >= off) e *= y;
    }

    // Scale per-segment accumulators by entering transmittance, then warp sum.
    r *= e; g *= e; b *= e; d *= e;
#pragma unroll
    for (int off = 16; off > 0; off >>= 1) {
        r += __shfl_down_sync(FULL, r, off);
        g += __shfl_down_sync(FULL, g, off);
        b += __shfl_down_sync(FULL, b, off);
        d += __shfl_down_sync(FULL, d, off);
    }

    if (lane == 0) {
        out[ray * 3 + 0] = r;
        out[ray * 3 + 1] = g;
        out[ray * 3 + 2] = b;
        out[(size_t)n_rays * 3 + ray] = d;
    }
}

extern "C" void kernel_launch(void* const* d_in, const int* in_sizes, int n_in,
                              void* d_out, int out_size)
{
    // color = largest input; the other two are sigma/t (disambiguated on device).
    int color_idx = 0;
    for (int i = 1; i < 3; i++)
        if (in_sizes[i] > in_sizes[color_idx]) color_idx = i;

    int a_idx = -1, b_idx = -1;
    for (int i = 0; i < 3; i++) {
        if (i == color_idx) continue;
        if (a_idx < 0) a_idx = i; else b_idx = i;
    }

    const float* pa    = (const float*)d_in[a_idx];
    const float* pb    = (const float*)d_in[b_idx];
    const float* color = (const float*)d_in[color_idx];
    float* out = (float*)d_out;

    int n_rays = in_sizes[a_idx] / N_SAMPLES;

    const int threads = 256;                      // 8 warps = 8 rays per block
    long long total_threads = (long long)n_rays * 32;
    int blocks = (int)((total_threads + threads - 1) / threads);
    render_kernel<<<blocks, threads>>>(pa, pb, color, out, n_rays);
}